// round 3
// baseline (speedup 1.0000x reference)
#include <cuda_runtime.h>

// Shapes (fixed by the problem)
#define B_  8
#define C_  256
#define MID_ 16
#define H_  128
#define W_  128
#define HW_ (H_*W_)      // 16384
#define KK  7
#define PADK 3

// Scratch (no allocs allowed): x_low and out_low, (B,MID,H,W) each = 8MB
__device__ float g_xlow[B_*MID_*HW_];
__device__ float g_outlow[B_*MID_*HW_];
// Packed weights: for each c, 8 u64 = (m0,m1),(m2,m3)...(m14,m15)
__device__ unsigned long long g_wr2[C_*8];
__device__ unsigned long long g_we2[C_*8];

// ---- packed f32x2 helpers (sm_103a) ----
static __device__ __forceinline__ unsigned long long pack2(float lo, float hi) {
    unsigned long long r;
    asm("mov.b64 %0, {%1, %2};" : "=l"(r) : "f"(lo), "f"(hi));
    return r;
}
static __device__ __forceinline__ void unpack2(unsigned long long v, float& lo, float& hi) {
    asm("mov.b64 {%0, %1}, %2;" : "=f"(lo), "=f"(hi) : "l"(v));
}
static __device__ __forceinline__ unsigned long long ffma2(
    unsigned long long a, unsigned long long b, unsigned long long c) {
    unsigned long long d;
    asm("fma.rn.f32x2 %0, %1, %2, %3;" : "=l"(d) : "l"(a), "l"(b), "l"(c));
    return d;
}

// ---------------------------------------------------------------------------
// K0: pack weights into m-pair u64 form
// w_reduce: (MID, C) row-major ; w_expand: (C, MID) row-major
// ---------------------------------------------------------------------------
__global__ void k_pack_weights(const float* __restrict__ wr,
                               const float* __restrict__ we) {
    int i = blockIdx.x * blockDim.x + threadIdx.x;   // 0..2047
    if (i < C_*8) {
        int c = i >> 3, q = i & 7;
        g_wr2[i] = pack2(wr[(2*q)   * C_ + c], wr[(2*q+1) * C_ + c]);
        g_we2[i] = pack2(we[c * MID_ + 2*q],   we[c * MID_ + 2*q + 1]);
    }
}

// ---------------------------------------------------------------------------
// K1: x_low[b,m,h,w] = sum_c x[b,c,h,w] * w_reduce[m,c]
// 1 thread = 1 pixel, all 16 m packed as 8 f32x2 accumulators.
// ---------------------------------------------------------------------------
__global__ __launch_bounds__(256) void k_reduce(const float* __restrict__ x) {
    __shared__ unsigned long long s_w[C_*8];   // 16 KB
    int tid = threadIdx.x;
    #pragma unroll
    for (int i = tid; i < C_*8; i += 256) s_w[i] = g_wr2[i];
    __syncthreads();

    int p  = blockIdx.x * 256 + tid;     // pixel 0..131071
    int b  = p >> 14;                    // /16384
    int hw = p & (HW_ - 1);

    const float* xp = x + (long)b * C_ * HW_ + hw;

    unsigned long long acc[8];
    #pragma unroll
    for (int q = 0; q < 8; q++) acc[q] = 0ULL;

    #pragma unroll 4
    for (int c = 0; c < C_; c++) {
        float v = xp[c * HW_];
        unsigned long long v2 = pack2(v, v);
        const ulonglong2* wrow = reinterpret_cast<const ulonglong2*>(&s_w[c*8]);
        ulonglong2 w01 = wrow[0];
        ulonglong2 w23 = wrow[1];
        ulonglong2 w45 = wrow[2];
        ulonglong2 w67 = wrow[3];
        acc[0] = ffma2(v2, w01.x, acc[0]);
        acc[1] = ffma2(v2, w01.y, acc[1]);
        acc[2] = ffma2(v2, w23.x, acc[2]);
        acc[3] = ffma2(v2, w23.y, acc[3]);
        acc[4] = ffma2(v2, w45.x, acc[4]);
        acc[5] = ffma2(v2, w45.y, acc[5]);
        acc[6] = ffma2(v2, w67.x, acc[6]);
        acc[7] = ffma2(v2, w67.y, acc[7]);
    }

    float* op = g_xlow + (long)b * MID_ * HW_ + hw;
    #pragma unroll
    for (int q = 0; q < 8; q++) {
        float lo, hi;
        unpack2(acc[q], lo, hi);
        op[(2*q)   * HW_] = lo;
        op[(2*q+1) * HW_] = hi;
    }
}

// ---------------------------------------------------------------------------
// K2: out_low = w_h*(x_low (*) BASE_H) + (1-w_h)*(x_low (*) BASE_V)
// BASE_H[i][j] = f(i)*g(j)/S,  BASE_V[i][j] = g(i)*f(j)/S, computed in-kernel.
// Tiled 32x16, reflect padding, 1 thread = 1 output pixel of one (b,m) plane.
// ---------------------------------------------------------------------------
#define TILE_H 16
#define TILE_W 32
#define HALO_W (TILE_W + 6)
#define HALO_H (TILE_H + 6)

__global__ __launch_bounds__(TILE_H*TILE_W) void k_conv(const float* __restrict__ angle) {
    __shared__ float s_t[HALO_H * HALO_W];
    __shared__ float s_bh[49];
    __shared__ float s_bv[49];

    int tid = threadIdx.y * TILE_W + threadIdx.x;

    if (tid < 49) {
        int i = tid / 7, j = tid % 7;
        float ai = (float)(i - 3), aj = (float)(j - 3);
        float sf = 0.f, sg = 0.f;
        #pragma unroll
        for (int t = 0; t < 7; t++) {
            float a = (float)(t - 3);
            sf += expf(-a*a / 12.5f);
            sg += expf(-a*a * 0.5f);
        }
        float inv = 1.f / (sf * sg + 1e-8f);
        float fi = expf(-ai*ai / 12.5f), gi = expf(-ai*ai * 0.5f);
        float fj = expf(-aj*aj / 12.5f), gj = expf(-aj*aj * 0.5f);
        s_bh[tid] = fi * gj * inv;   // BASE_H
        s_bv[tid] = gi * fj * inv;   // BASE_V = BASE_H^T
    }

    int bz = blockIdx.z;             // b*16 + m
    int b  = bz >> 4;
    int h0 = blockIdx.y * TILE_H;
    int w0 = blockIdx.x * TILE_W;

    const float* xl = g_xlow + (long)bz * HW_;
    for (int idx = tid; idx < HALO_H * HALO_W; idx += TILE_H * TILE_W) {
        int hh = idx / HALO_W, ww = idx % HALO_W;
        int gh = h0 + hh - PADK;
        int gw = w0 + ww - PADK;
        gh = gh < 0 ? -gh : (gh > H_-1 ? 2*(H_-1) - gh : gh);   // reflect
        gw = gw < 0 ? -gw : (gw > W_-1 ? 2*(W_-1) - gw : gw);
        s_t[idx] = xl[gh * W_ + gw];
    }
    __syncthreads();

    float aH = 0.f, aV = 0.f;
    #pragma unroll
    for (int i = 0; i < 7; i++) {
        #pragma unroll
        for (int j = 0; j < 7; j++) {
            float v = s_t[(threadIdx.y + i) * HALO_W + threadIdx.x + j];
            aH += v * s_bh[i*7 + j];
            aV += v * s_bv[i*7 + j];
        }
    }

    int h = h0 + threadIdx.y, w = w0 + threadIdx.x;
    float ang = angle[b * HW_ + h * W_ + w];
    float cw = cosf(ang);
    float wh = cw * cw;
    g_outlow[(long)bz * HW_ + h * W_ + w] = wh * aH + (1.f - wh) * aV;
}

// ---------------------------------------------------------------------------
// K3: out[b,c,h,w] = sum_m out_low[b,m,h,w] * w_expand[c,m]
// 1 thread = 1 pixel; out_low held as 8 packed m-pairs; 8 FFMA2 per channel.
// ---------------------------------------------------------------------------
__global__ __launch_bounds__(256) void k_expand(float* __restrict__ out) {
    __shared__ unsigned long long s_w[C_*8];   // 16 KB
    int tid = threadIdx.x;
    #pragma unroll
    for (int i = tid; i < C_*8; i += 256) s_w[i] = g_we2[i];
    __syncthreads();

    int p  = blockIdx.x * 256 + tid;
    int b  = p >> 14;
    int hw = p & (HW_ - 1);

    const float* olp = g_outlow + (long)b * MID_ * HW_ + hw;
    unsigned long long ol2[8];
    #pragma unroll
    for (int q = 0; q < 8; q++)
        ol2[q] = pack2(olp[(2*q) * HW_], olp[(2*q+1) * HW_]);

    float* op = out + (long)b * C_ * HW_ + hw;

    #pragma unroll 4
    for (int c = 0; c < C_; c++) {
        const ulonglong2* wrow = reinterpret_cast<const ulonglong2*>(&s_w[c*8]);
        ulonglong2 w01 = wrow[0];
        ulonglong2 w23 = wrow[1];
        ulonglong2 w45 = wrow[2];
        ulonglong2 w67 = wrow[3];
        unsigned long long acc = 0ULL;
        acc = ffma2(ol2[0], w01.x, acc);
        acc = ffma2(ol2[1], w01.y, acc);
        acc = ffma2(ol2[2], w23.x, acc);
        acc = ffma2(ol2[3], w23.y, acc);
        acc = ffma2(ol2[4], w45.x, acc);
        acc = ffma2(ol2[5], w45.y, acc);
        acc = ffma2(ol2[6], w67.x, acc);
        acc = ffma2(ol2[7], w67.y, acc);
        float lo, hi;
        unpack2(acc, lo, hi);
        op[c * HW_] = lo + hi;
    }
}

// ---------------------------------------------------------------------------
extern "C" void kernel_launch(void* const* d_in, const int* in_sizes, int n_in,
                              void* d_out, int out_size) {
    const float* x      = (const float*)d_in[0];   // (8,256,128,128)
    const float* angle  = (const float*)d_in[1];   // (8,128,128)
    const float* wr     = (const float*)d_in[2];   // (16,256)
    const float* we     = (const float*)d_in[3];   // (256,16)
    float* out          = (float*)d_out;           // (8,256,128,128)

    (void)in_sizes; (void)n_in; (void)out_size;

    k_pack_weights<<<8, 256>>>(wr, we);

    // 131072 pixels / 256 threads
    k_reduce<<<B_*HW_/2 / 256 * 2 / 256 * 256 >= 0 ? 512 : 512, 256>>>(x);

    dim3 cgrid(W_/TILE_W, H_/TILE_H, B_*MID_);     // (4, 8, 128)
    dim3 cblk(TILE_W, TILE_H);
    k_conv<<<cgrid, cblk>>>(angle);

    k_expand<<<512, 256>>>(out);
}

// round 4
// speedup vs baseline: 1.4386x; 1.4386x over previous
#include <cuda_runtime.h>

// Shapes (fixed by the problem)
#define B_   8
#define C_   256
#define MID_ 16
#define H_   128
#define W_   128
#define HW_  (H_*W_)      // 16384
#define PADK 3

// Scratch (no allocs allowed): x_low and out_low, (B,MID,H,W) each = 8MB
__device__ float g_xlow[B_*MID_*HW_];
__device__ float g_outlow[B_*MID_*HW_];
// Packed weights: for each c, 8 u64 = (m0,m1),(m2,m3)...(m14,m15)
__device__ unsigned long long g_wr2[C_*8];
__device__ unsigned long long g_we2[C_*8];

// ---- packed f32x2 helpers (sm_103a) ----
static __device__ __forceinline__ unsigned long long pack2(float lo, float hi) {
    unsigned long long r;
    asm("mov.b64 %0, {%1, %2};" : "=l"(r) : "f"(lo), "f"(hi));
    return r;
}
static __device__ __forceinline__ void unpack2(unsigned long long v, float& lo, float& hi) {
    asm("mov.b64 {%0, %1}, %2;" : "=f"(lo), "=f"(hi) : "l"(v));
}
static __device__ __forceinline__ unsigned long long ffma2(
    unsigned long long a, unsigned long long b, unsigned long long c) {
    unsigned long long d;
    asm("fma.rn.f32x2 %0, %1, %2, %3;" : "=l"(d) : "l"(a), "l"(b), "l"(c));
    return d;
}

// ---------------------------------------------------------------------------
// K0: pack weights into m-pair u64 form
// w_reduce: (MID, C) row-major ; w_expand: (C, MID) row-major
// ---------------------------------------------------------------------------
__global__ void k_pack_weights(const float* __restrict__ wr,
                               const float* __restrict__ we) {
    int i = blockIdx.x * blockDim.x + threadIdx.x;   // 0..2047
    if (i < C_*8) {
        int c = i >> 3, q = i & 7;
        g_wr2[i] = pack2(wr[(2*q)   * C_ + c], wr[(2*q+1) * C_ + c]);
        g_we2[i] = pack2(we[c * MID_ + 2*q],   we[c * MID_ + 2*q + 1]);
    }
}

// ---------------------------------------------------------------------------
// K1: x_low[b,m,h,w] = sum_c x[b,c,h,w] * w_reduce[m,c]
// 1 thread = 1 pixel, 16 m packed as 8 f32x2 accumulators.
// Explicit 16-deep load batching for MLP; __ldcs (read-once stream).
// ---------------------------------------------------------------------------
__global__ __launch_bounds__(256) void k_reduce(const float* __restrict__ x) {
    __shared__ unsigned long long s_w[C_*8];   // 16 KB
    int tid = threadIdx.x;
    #pragma unroll
    for (int i = tid; i < C_*8; i += 256) s_w[i] = g_wr2[i];
    __syncthreads();

    int p  = blockIdx.x * 256 + tid;     // pixel 0..131071
    int b  = p >> 14;
    int hw = p & (HW_ - 1);

    const float* xp = x + (long)b * C_ * HW_ + hw;

    unsigned long long acc[8];
    #pragma unroll
    for (int q = 0; q < 8; q++) acc[q] = 0ULL;

    #pragma unroll
    for (int c0 = 0; c0 < C_; c0 += 16) {
        float vv[16];
        #pragma unroll
        for (int u = 0; u < 16; u++)
            vv[u] = __ldcs(xp + (long)(c0 + u) * HW_);
        #pragma unroll
        for (int u = 0; u < 16; u++) {
            unsigned long long v2 = pack2(vv[u], vv[u]);
            const ulonglong2* wrow =
                reinterpret_cast<const ulonglong2*>(&s_w[(c0 + u) * 8]);
            ulonglong2 w01 = wrow[0];
            ulonglong2 w23 = wrow[1];
            ulonglong2 w45 = wrow[2];
            ulonglong2 w67 = wrow[3];
            acc[0] = ffma2(v2, w01.x, acc[0]);
            acc[1] = ffma2(v2, w01.y, acc[1]);
            acc[2] = ffma2(v2, w23.x, acc[2]);
            acc[3] = ffma2(v2, w23.y, acc[3]);
            acc[4] = ffma2(v2, w45.x, acc[4]);
            acc[5] = ffma2(v2, w45.y, acc[5]);
            acc[6] = ffma2(v2, w67.x, acc[6]);
            acc[7] = ffma2(v2, w67.y, acc[7]);
        }
    }

    float* op = g_xlow + (long)b * MID_ * HW_ + hw;
    #pragma unroll
    for (int q = 0; q < 8; q++) {
        float lo, hi;
        unpack2(acc[q], lo, hi);
        op[(2*q)   * HW_] = lo;
        op[(2*q+1) * HW_] = hi;
    }
}

// ---------------------------------------------------------------------------
// K2: out_low = w_h*(x_low (*) BASE_H) + (1-w_h)*(x_low (*) BASE_V)
// Separable: BASE_H[i][j] = f(i)g(j)/S, BASE_V[i][j] = g(i)f(j)/S.
//   aH = inv * sum_i f(i) * Hg(i),  Hg(i) = sum_j g(j) v(i,j)
//   aV = inv * sum_i g(i) * Hf(i),  Hf(i) = sum_j f(j) v(i,j)
// All taps are compile-time literals -> FFMA-imm (rt=1), zero weight LDS.
// ---------------------------------------------------------------------------
#define TILE_H 16
#define TILE_W 32
#define HALO_H (TILE_H + 6)          // 22
#define HALO_W (TILE_W + 6)          // 38

// f(a)=exp(-a^2/12.5), g(a)=exp(-a^2/2), a=-3..3
#define F0 0.48675225595997157f
#define F1 0.7261490370736909f
#define F2 0.9231163463866358f
#define F3 1.0f
#define G0 0.011108996538242306f
#define G1 0.1353352832366127f
#define G2 0.6065306597126334f
#define G3 1.0f
#define SUMF (F3 + 2.0f*(F0 + F1 + F2))
#define SUMG (G3 + 2.0f*(G0 + G1 + G2))
#define INVS (1.0f/(SUMF*SUMG + 1e-8f))

__global__ __launch_bounds__(TILE_H*TILE_W) void k_conv(const float* __restrict__ angle) {
    __shared__ float  s_t[HALO_H * HALO_W];          // raw tile + halo
    __shared__ float2 s_hf[HALO_H * TILE_W];         // (Hg, Hf) per position

    const float Fk[7] = {F0, F1, F2, F3, F2, F1, F0};
    const float Gk[7] = {G0, G1, G2, G3, G2, G1, G0};

    int tid = threadIdx.y * TILE_W + threadIdx.x;
    int bz  = blockIdx.z;             // b*16 + m
    int b   = bz >> 4;
    int h0  = blockIdx.y * TILE_H;
    int w0  = blockIdx.x * TILE_W;

    // load halo tile with reflect padding
    const float* xl = g_xlow + (long)bz * HW_;
    for (int idx = tid; idx < HALO_H * HALO_W; idx += TILE_H * TILE_W) {
        int hh = idx / HALO_W, ww = idx - hh * HALO_W;
        int gh = h0 + hh - PADK;
        int gw = w0 + ww - PADK;
        gh = gh < 0 ? -gh : (gh > H_-1 ? 2*(H_-1) - gh : gh);
        gw = gw < 0 ? -gw : (gw > W_-1 ? 2*(W_-1) - gw : gw);
        s_t[idx] = xl[gh * W_ + gw];
    }
    __syncthreads();

    // stage 1: horizontal 1-D passes (g and f), 704 positions / 512 threads
    for (int idx = tid; idx < HALO_H * TILE_W; idx += TILE_H * TILE_W) {
        int r = idx >> 5;            // row 0..21
        int x = idx & 31;
        const float* row = s_t + r * HALO_W + x;
        float hg = 0.f, hf = 0.f;
        #pragma unroll
        for (int j = 0; j < 7; j++) {
            float v = row[j];
            hg = fmaf(v, Gk[j], hg);
            hf = fmaf(v, Fk[j], hf);
        }
        s_hf[idx] = make_float2(hg, hf);
    }
    __syncthreads();

    // stage 2: vertical 1-D passes (f on Hg, g on Hf), inv folded in
    float aH = 0.f, aV = 0.f;
    #pragma unroll
    for (int i = 0; i < 7; i++) {
        float2 hv = s_hf[(threadIdx.y + i) * TILE_W + threadIdx.x];
        aH = fmaf(hv.x, Fk[i] * INVS, aH);
        aV = fmaf(hv.y, Gk[i] * INVS, aV);
    }

    int h = h0 + threadIdx.y, w = w0 + threadIdx.x;
    float ang = angle[b * HW_ + h * W_ + w];
    float cw  = cosf(ang);
    float wh  = cw * cw;
    g_outlow[(long)bz * HW_ + h * W_ + w] = wh * aH + (1.f - wh) * aV;
}

// ---------------------------------------------------------------------------
// K3: out[b,c,h,w] = sum_m out_low[b,m,h,w] * w_expand[c,m]
// 2 pixels per thread: weight LDS amortized x2, two independent acc chains,
// STG.64 streaming stores.
// ---------------------------------------------------------------------------
__global__ __launch_bounds__(256) void k_expand(float* __restrict__ out) {
    __shared__ unsigned long long s_w[C_*8];   // 16 KB
    int tid = threadIdx.x;
    #pragma unroll
    for (int i = tid; i < C_*8; i += 256) s_w[i] = g_we2[i];
    __syncthreads();

    int t  = blockIdx.x * 256 + tid;     // 0..65535
    int pp = t * 2;                      // pixel pair base
    int b  = pp >> 14;
    int hw = pp & (HW_ - 1);

    const float* olp = g_outlow + (long)b * MID_ * HW_ + hw;

    // olA[q] = (m=2q, m=2q+1) for pixel hw ; olB[q] = same for pixel hw+1
    unsigned long long olA[8], olB[8];
    #pragma unroll
    for (int q = 0; q < 8; q++) {
        float2 e = *reinterpret_cast<const float2*>(olp + (long)(2*q)   * HW_);
        float2 o = *reinterpret_cast<const float2*>(olp + (long)(2*q+1) * HW_);
        olA[q] = pack2(e.x, o.x);
        olB[q] = pack2(e.y, o.y);
    }

    float* op = out + (long)b * C_ * HW_ + hw;

    #pragma unroll 4
    for (int c = 0; c < C_; c++) {
        const ulonglong2* wrow = reinterpret_cast<const ulonglong2*>(&s_w[c*8]);
        ulonglong2 w01 = wrow[0];
        ulonglong2 w23 = wrow[1];
        ulonglong2 w45 = wrow[2];
        ulonglong2 w67 = wrow[3];
        unsigned long long a0 = 0ULL, a1 = 0ULL;
        a0 = ffma2(olA[0], w01.x, a0);   a1 = ffma2(olB[0], w01.x, a1);
        a0 = ffma2(olA[1], w01.y, a0);   a1 = ffma2(olB[1], w01.y, a1);
        a0 = ffma2(olA[2], w23.x, a0);   a1 = ffma2(olB[2], w23.x, a1);
        a0 = ffma2(olA[3], w23.y, a0);   a1 = ffma2(olB[3], w23.y, a1);
        a0 = ffma2(olA[4], w45.x, a0);   a1 = ffma2(olB[4], w45.x, a1);
        a0 = ffma2(olA[5], w45.y, a0);   a1 = ffma2(olB[5], w45.y, a1);
        a0 = ffma2(olA[6], w67.x, a0);   a1 = ffma2(olB[6], w67.x, a1);
        a0 = ffma2(olA[7], w67.y, a0);   a1 = ffma2(olB[7], w67.y, a1);
        float l0, h0v, l1, h1v;
        unpack2(a0, l0, h0v);
        unpack2(a1, l1, h1v);
        float2 r = make_float2(l0 + h0v, l1 + h1v);
        __stcs(reinterpret_cast<float2*>(op + (long)c * HW_), r);
    }
}

// ---------------------------------------------------------------------------
extern "C" void kernel_launch(void* const* d_in, const int* in_sizes, int n_in,
                              void* d_out, int out_size) {
    const float* x      = (const float*)d_in[0];   // (8,256,128,128)
    const float* angle  = (const float*)d_in[1];   // (8,128,128)
    const float* wr     = (const float*)d_in[2];   // (16,256)
    const float* we     = (const float*)d_in[3];   // (256,16)
    float* out          = (float*)d_out;           // (8,256,128,128)

    (void)in_sizes; (void)n_in; (void)out_size;

    k_pack_weights<<<8, 256>>>(wr, we);

    k_reduce<<<512, 256>>>(x);                      // 131072 px / 256

    dim3 cgrid(W_/TILE_W, H_/TILE_H, B_*MID_);      // (4, 8, 128)
    dim3 cblk(TILE_W, TILE_H);
    k_conv<<<cgrid, cblk>>>(angle);

    k_expand<<<256, 256>>>(out);                    // 65536 threads, 2 px each
}